// round 14
// baseline (speedup 1.0000x reference)
#include <cuda_runtime.h>

// Batched Kalman step: B=131072, STATE=16, OBS=8.
// 4 lanes per batch: lane t owns state rows {t,t+4,t+8,t+12}, obs rows {t,t+4}.
// 8 batches per warp, 32 per 128-thread block, 4 blocks/SM spill-free:
//  - resid first (packed-H regs die at top)
//  - PHt never held in registers: unpacked straight to smem WT; triangular
//    solves read their RHS from WT
//  - phase 2 processes one obs row at a time with L1-hot H re-reads
//  - phase 7 consumes F in halves; phase 8 = dot products vs F rows in smem.

using ull = unsigned long long;
using u2  = ulonglong2;

__device__ __forceinline__ ull pk2(float lo, float hi) {
    ull r; asm("mov.b64 %0, {%1,%2};" : "=l"(r) : "f"(lo), "f"(hi)); return r;
}
__device__ __forceinline__ ull pk1(float x) {
    ull r; asm("mov.b64 %0, {%1,%1};" : "=l"(r) : "f"(x)); return r;
}
__device__ __forceinline__ void upk(ull v, float& lo, float& hi) {
    asm("mov.b64 {%0,%1}, %2;" : "=f"(lo), "=f"(hi) : "l"(v));
}
__device__ __forceinline__ ull ffma2(ull a, ull b, ull c) {
    ull d; asm("fma.rn.f32x2 %0, %1, %2, %3;" : "=l"(d) : "l"(a), "l"(b), "l"(c)); return d;
}
__device__ __forceinline__ ull add2(ull a, ull b) {
    ull d; asm("add.rn.f32x2 %0, %1, %2;" : "=l"(d) : "l"(a), "l"(b)); return d;
}
__device__ __forceinline__ float hsum(ull a) {
    float lo, hi; upk(a, lo, hi); return lo + hi;
}

static constexpr int GB  = 32;       // batches per block
static constexpr int TPB = 128;      // 4 lanes per batch
static constexpr int SB    = 324;    // per-batch smem floats; ≡4 mod 32 banks
static constexpr int XO    = 0;      // 16x16 region: HT -> WT/SS -> NC -> Frows
static constexpr int WTO   = 0;
static constexpr int SSO   = 128;
static constexpr int SMEAN = 256;
static constexpr int SRES  = 272;
static constexpr int SNM   = 280;

__global__ void __launch_bounds__(TPB, 4) kf_step(
    const float* __restrict__ gin,  const float* __restrict__ gmean,
    const float* __restrict__ gcov, const float* __restrict__ gH,
    const float* __restrict__ gR,   const float* __restrict__ gF,
    const float* __restrict__ gQ,
    float* __restrict__ omean, float* __restrict__ ocov, int nb)
{
    __shared__ __align__(16) float sm[GB * SB];
    const int g = threadIdx.x >> 2;
    const int t = threadIdx.x & 3;
    long long b = (long long)blockIdx.x * GB + g;
    const bool valid = (b < nb);
    if (!valid) b = nb - 1;
    float* S = sm + g * SB;

    int rr[4];
#pragma unroll
    for (int k = 0; k < 4; k++) rr[k] = t + 4 * k;

    // ---- top: H rows t,t+4 (packed) -> scatter H^T into X; mean; resid ----
    float m[4];
    {
        ull hpA[8], hpB[8];
        const float4* H4 = reinterpret_cast<const float4*>(gH + b * 128);
#pragma unroll
        for (int q = 0; q < 4; q++) {
            float4 va = H4[t * 4 + q];
            hpA[2*q] = pk2(va.x, va.y); hpA[2*q+1] = pk2(va.z, va.w);
            S[XO + (4*q+0)*16 + t] = va.x; S[XO + (4*q+1)*16 + t] = va.y;
            S[XO + (4*q+2)*16 + t] = va.z; S[XO + (4*q+3)*16 + t] = va.w;
            float4 vb = H4[(t + 4) * 4 + q];
            hpB[2*q] = pk2(vb.x, vb.y); hpB[2*q+1] = pk2(vb.z, vb.w);
            S[XO + (4*q+0)*16 + t+4] = vb.x; S[XO + (4*q+1)*16 + t+4] = vb.y;
            S[XO + (4*q+2)*16 + t+4] = vb.z; S[XO + (4*q+3)*16 + t+4] = vb.w;
        }
#pragma unroll
        for (int k = 0; k < 4; k++) { m[k] = gmean[b * 16 + rr[k]]; S[SMEAN + rr[k]] = m[k]; }
        __syncwarp();

        float eA = gin[b * 8 + t], eB = gin[b * 8 + t + 4];
        const float* mp = &S[SMEAN];
        u2 q0 = *reinterpret_cast<const u2*>(mp);
        u2 q1 = *reinterpret_cast<const u2*>(mp + 4);
        u2 q2 = *reinterpret_cast<const u2*>(mp + 8);
        u2 q3 = *reinterpret_cast<const u2*>(mp + 12);
        ull a0 = ffma2(hpA[0], q0.x, 0ull), a1 = ffma2(hpA[1], q0.y, 0ull);
        a0 = ffma2(hpA[2], q1.x, a0); a1 = ffma2(hpA[3], q1.y, a1);
        a0 = ffma2(hpA[4], q2.x, a0); a1 = ffma2(hpA[5], q2.y, a1);
        a0 = ffma2(hpA[6], q3.x, a0); a1 = ffma2(hpA[7], q3.y, a1);
        S[SRES + t] = eA - hsum(add2(a0, a1));
        ull b0 = ffma2(hpB[0], q0.x, 0ull), b1 = ffma2(hpB[1], q0.y, 0ull);
        b0 = ffma2(hpB[2], q1.x, b0); b1 = ffma2(hpB[3], q1.y, b1);
        b0 = ffma2(hpB[4], q2.x, b0); b1 = ffma2(hpB[5], q2.y, b1);
        b0 = ffma2(hpB[6], q3.x, b0); b1 = ffma2(hpB[7], q3.y, b1);
        S[SRES + t + 4] = eB - hsum(add2(b0, b1));
    }   // hpA/hpB dead

    // ---- phase 1: ph[k] = packed PHt row rr[k]; cov held whole, then dies ----
    ull ph[4][4];
#pragma unroll
    for (int k = 0; k < 4; k++)
#pragma unroll
        for (int p = 0; p < 4; p++) ph[k][p] = 0ull;
    {
        const float4* P4 = reinterpret_cast<const float4*>(gcov + b * 256);
        float c[4][16];
#pragma unroll
        for (int k = 0; k < 4; k++)
#pragma unroll
            for (int q = 0; q < 4; q++) {
                float4 v = P4[rr[k] * 4 + q];
                c[k][4*q] = v.x; c[k][4*q+1] = v.y; c[k][4*q+2] = v.z; c[k][4*q+3] = v.w;
            }
#pragma unroll
        for (int s = 0; s < 16; s++) {
            u2 hA = *reinterpret_cast<const u2*>(&S[XO + s * 16]);
            u2 hB = *reinterpret_cast<const u2*>(&S[XO + s * 16 + 4]);
#pragma unroll
            for (int k = 0; k < 4; k++) {
                ull cs = pk1(c[k][s]);
                ph[k][0] = ffma2(hA.x, cs, ph[k][0]); ph[k][1] = ffma2(hA.y, cs, ph[k][1]);
                ph[k][2] = ffma2(hB.x, cs, ph[k][2]); ph[k][3] = ffma2(hB.y, cs, ph[k][3]);
            }
        }
    }
    __syncwarp();   // all HT reads done before WT overlays X rows 0..7
    // unpack ph STRAIGHT into WT (no pht register array)
#pragma unroll
    for (int k = 0; k < 4; k++)
#pragma unroll
        for (int p = 0; p < 4; p++) {
            float lo, hi; upk(ph[k][p], lo, hi);
            S[WTO + (2*p)     * 16 + rr[k]] = lo;
            S[WTO + (2*p + 1) * 16 + rr[k]] = hi;
        }
    __syncwarp();

    // ---- phase 2: one obs row at a time (hp re-read L1-hot, R per row) ----
    {
        const float4* H4 = reinterpret_cast<const float4*>(gH + b * 128);
#pragma unroll
        for (int half = 0; half < 2; half++) {
            const int i = t + 4 * half;
            ull hp[8];
#pragma unroll
            for (int q = 0; q < 4; q++) {
                float4 v = H4[i * 4 + q];
                hp[2*q] = pk2(v.x, v.y); hp[2*q+1] = pk2(v.z, v.w);
            }
            float4 R0 = *reinterpret_cast<const float4*>(gR + b * 64 + i * 8);
            float4 R1 = *reinterpret_cast<const float4*>(gR + b * 64 + i * 8 + 4);
            float rv[8] = {R0.x,R0.y,R0.z,R0.w, R1.x,R1.y,R1.z,R1.w};
            float sv[8];
#pragma unroll
            for (int j = 0; j < 8; j++) {
                const float* wr = &S[WTO + j * 16];
                u2 w0 = *reinterpret_cast<const u2*>(wr);
                u2 w1 = *reinterpret_cast<const u2*>(wr + 4);
                u2 w2 = *reinterpret_cast<const u2*>(wr + 8);
                u2 w3 = *reinterpret_cast<const u2*>(wr + 12);
                ull a0 = ffma2(hp[0], w0.x, 0ull), a1 = ffma2(hp[1], w0.y, 0ull);
                a0 = ffma2(hp[2], w1.x, a0); a1 = ffma2(hp[3], w1.y, a1);
                a0 = ffma2(hp[4], w2.x, a0); a1 = ffma2(hp[5], w2.y, a1);
                a0 = ffma2(hp[6], w3.x, a0); a1 = ffma2(hp[7], w3.y, a1);
                sv[j] = rv[j] + hsum(add2(a0, a1));
            }
            float4* sd = reinterpret_cast<float4*>(&S[SSO + i * 8]);
            sd[0] = make_float4(sv[0], sv[1], sv[2], sv[3]);
            sd[1] = make_float4(sv[4], sv[5], sv[6], sv[7]);
        }
    }
    __syncwarp();   // SS visible

    // ---- phase 3: redundant per-lane Cholesky; solves read RHS from WT ----
    float L[28], dinv[8];
#pragma unroll
    for (int j = 0; j < 8; j++) {
        float d = S[SSO + j * 8 + j];
#pragma unroll
        for (int k2 = 0; k2 < j; k2++) d -= L[j*(j-1)/2 + k2] * L[j*(j-1)/2 + k2];
        float inv = rsqrtf(d);
        dinv[j] = inv;
#pragma unroll
        for (int i2 = j + 1; i2 < 8; i2++) {
            float e = S[SSO + i2 * 8 + j];
#pragma unroll
            for (int k2 = 0; k2 < j; k2++) e -= L[i2*(i2-1)/2 + k2] * L[j*(j-1)/2 + k2];
            L[i2*(i2-1)/2 + j] = e * inv;
        }
    }
    float K[4][8];
#pragma unroll
    for (int k = 0; k < 4; k++) {
        float y[8];
#pragma unroll
        for (int j = 0; j < 8; j++) {
            float e = S[WTO + j * 16 + rr[k]];   // RHS = PHt row from smem
#pragma unroll
            for (int k2 = 0; k2 < j; k2++) e -= L[j*(j-1)/2 + k2] * y[k2];
            y[j] = e * dinv[j];
        }
#pragma unroll
        for (int j = 7; j >= 0; j--) {
            float e = y[j];
#pragma unroll
            for (int k2 = j + 1; k2 < 8; k2++) e -= L[k2*(k2-1)/2 + j] * K[k][k2];
            K[k][j] = e * dinv[j];
        }
    }

    // ---- new_mean rows -> SNM ----
    {
        u2 e0 = *reinterpret_cast<const u2*>(&S[SRES]);
        u2 e1 = *reinterpret_cast<const u2*>(&S[SRES + 4]);
#pragma unroll
        for (int k = 0; k < 4; k++) {
            ull a0 = ffma2(pk2(K[k][0], K[k][1]), e0.x, 0ull);
            ull a1 = ffma2(pk2(K[k][2], K[k][3]), e0.y, 0ull);
            a0 = ffma2(pk2(K[k][4], K[k][5]), e1.x, a0);
            a1 = ffma2(pk2(K[k][6], K[k][7]), e1.y, a1);
            S[SNM + rr[k]] = m[k] + hsum(add2(a0, a1));
        }
    }

    // ---- phase 6: NC rows = cov - K.W  (cov re-loaded, L2-hot) ----
    ull nc[4][8];
    {
        const float4* P4 = reinterpret_cast<const float4*>(gcov + b * 256);
#pragma unroll
        for (int k = 0; k < 4; k++)
#pragma unroll
            for (int q = 0; q < 4; q++) {
                float4 v = P4[rr[k] * 4 + q];
                nc[k][2*q] = pk2(v.x, v.y); nc[k][2*q+1] = pk2(v.z, v.w);
            }
    }
#pragma unroll
    for (int o = 0; o < 8; o++) {
        const float* wr = &S[WTO + o * 16];
        u2 w0 = *reinterpret_cast<const u2*>(wr);
        u2 w1 = *reinterpret_cast<const u2*>(wr + 4);
        u2 w2 = *reinterpret_cast<const u2*>(wr + 8);
        u2 w3 = *reinterpret_cast<const u2*>(wr + 12);
#pragma unroll
        for (int k = 0; k < 4; k++) {
            ull nk = pk1(-K[k][o]);
            nc[k][0] = ffma2(w0.x, nk, nc[k][0]); nc[k][1] = ffma2(w0.y, nk, nc[k][1]);
            nc[k][2] = ffma2(w1.x, nk, nc[k][2]); nc[k][3] = ffma2(w1.y, nk, nc[k][3]);
            nc[k][4] = ffma2(w2.x, nk, nc[k][4]); nc[k][5] = ffma2(w2.y, nk, nc[k][5]);
            nc[k][6] = ffma2(w3.x, nk, nc[k][6]); nc[k][7] = ffma2(w3.y, nk, nc[k][7]);
        }
    }
    __syncwarp();   // all WT/SS reads complete before NC overlays X
    {
        const int ro = t & 2;   // chunk rotation vs 16t-mod-32 bank aliasing
#pragma unroll
        for (int k = 0; k < 4; k++) {
            u2* nr = reinterpret_cast<u2*>(&S[XO + rr[k] * 16]);
#pragma unroll
            for (int jj = 0; jj < 4; jj++) {
                int cj = (jj + ro) & 3;
                nr[cj] = make_ulonglong2(nc[k][2*cj], nc[k][2*cj+1]);
            }
        }
    }
    __syncwarp();   // NC + SNM visible

    // ---- phase 7 (F in halves) + pred_mean ----
    ull tp[4][8];
#pragma unroll
    for (int k = 0; k < 4; k++)
#pragma unroll
        for (int p = 0; p < 8; p++) tp[k][p] = 0ull;
    ull pa[4];
    {   // f_lo: F[rr[k]][0..7]
        const float4* F4 = reinterpret_cast<const float4*>(gF + b * 256);
        float fl[4][8];
#pragma unroll
        for (int k = 0; k < 4; k++)
#pragma unroll
            for (int q = 0; q < 2; q++) {
                float4 v = F4[rr[k] * 4 + q];
                fl[k][4*q] = v.x; fl[k][4*q+1] = v.y; fl[k][4*q+2] = v.z; fl[k][4*q+3] = v.w;
            }
        u2 n0 = *reinterpret_cast<const u2*>(&S[SNM]);
        u2 n1 = *reinterpret_cast<const u2*>(&S[SNM + 4]);
#pragma unroll
        for (int k = 0; k < 4; k++) {
            pa[k] = ffma2(pk2(fl[k][0], fl[k][1]), n0.x, 0ull);
            pa[k] = ffma2(pk2(fl[k][2], fl[k][3]), n0.y, pa[k]);
            pa[k] = ffma2(pk2(fl[k][4], fl[k][5]), n1.x, pa[k]);
            pa[k] = ffma2(pk2(fl[k][6], fl[k][7]), n1.y, pa[k]);
        }
#pragma unroll
        for (int u = 0; u < 8; u++) {
            const float* nr = &S[XO + u * 16];
            u2 e0 = *reinterpret_cast<const u2*>(nr);
            u2 e1 = *reinterpret_cast<const u2*>(nr + 4);
            u2 e2 = *reinterpret_cast<const u2*>(nr + 8);
            u2 e3 = *reinterpret_cast<const u2*>(nr + 12);
#pragma unroll
            for (int k = 0; k < 4; k++) {
                ull fu = pk1(fl[k][u]);
                tp[k][0] = ffma2(e0.x, fu, tp[k][0]); tp[k][1] = ffma2(e0.y, fu, tp[k][1]);
                tp[k][2] = ffma2(e1.x, fu, tp[k][2]); tp[k][3] = ffma2(e1.y, fu, tp[k][3]);
                tp[k][4] = ffma2(e2.x, fu, tp[k][4]); tp[k][5] = ffma2(e2.y, fu, tp[k][5]);
                tp[k][6] = ffma2(e3.x, fu, tp[k][6]); tp[k][7] = ffma2(e3.y, fu, tp[k][7]);
            }
        }
    }
    {   // f_hi: finish pred_mean; phase 7 pass 2; write F hi cols to X
        const float4* F4 = reinterpret_cast<const float4*>(gF + b * 256);
        float fh[4][8];
#pragma unroll
        for (int k = 0; k < 4; k++)
#pragma unroll
            for (int q = 0; q < 2; q++) {
                float4 v = F4[rr[k] * 4 + 2 + q];
                fh[k][4*q] = v.x; fh[k][4*q+1] = v.y; fh[k][4*q+2] = v.z; fh[k][4*q+3] = v.w;
            }
        u2 n2 = *reinterpret_cast<const u2*>(&S[SNM + 8]);
        u2 n3 = *reinterpret_cast<const u2*>(&S[SNM + 12]);
#pragma unroll
        for (int k = 0; k < 4; k++) {
            pa[k] = ffma2(pk2(fh[k][0], fh[k][1]), n2.x, pa[k]);
            pa[k] = ffma2(pk2(fh[k][2], fh[k][3]), n2.y, pa[k]);
            pa[k] = ffma2(pk2(fh[k][4], fh[k][5]), n3.x, pa[k]);
            pa[k] = ffma2(pk2(fh[k][6], fh[k][7]), n3.y, pa[k]);
            if (valid) omean[b * 16 + rr[k]] = hsum(pa[k]);
        }
#pragma unroll
        for (int u = 8; u < 16; u++) {
            const float* nr = &S[XO + u * 16];
            u2 e0 = *reinterpret_cast<const u2*>(nr);
            u2 e1 = *reinterpret_cast<const u2*>(nr + 4);
            u2 e2 = *reinterpret_cast<const u2*>(nr + 8);
            u2 e3 = *reinterpret_cast<const u2*>(nr + 12);
#pragma unroll
            for (int k = 0; k < 4; k++) {
                ull fu = pk1(fh[k][u - 8]);
                tp[k][0] = ffma2(e0.x, fu, tp[k][0]); tp[k][1] = ffma2(e0.y, fu, tp[k][1]);
                tp[k][2] = ffma2(e1.x, fu, tp[k][2]); tp[k][3] = ffma2(e1.y, fu, tp[k][3]);
                tp[k][4] = ffma2(e2.x, fu, tp[k][4]); tp[k][5] = ffma2(e2.y, fu, tp[k][5]);
                tp[k][6] = ffma2(e3.x, fu, tp[k][6]); tp[k][7] = ffma2(e3.y, fu, tp[k][7]);
            }
        }
        __syncwarp();   // all NC reads done before F rows overlay X
        const int r1 = (t >> 1) & 1;
#pragma unroll
        for (int k = 0; k < 4; k++)
#pragma unroll
            for (int j = 0; j < 2; j++) {
                int cidx = (j + r1) & 1;
                int base = 4 * cidx;
                *reinterpret_cast<u2*>(&S[XO + rr[k] * 16 + 8 + 4 * cidx]) =
                    make_ulonglong2(pk2(fh[k][base], fh[k][base+1]),
                                    pk2(fh[k][base+2], fh[k][base+3]));
            }
    }
    {   // reload f_lo (L1-hot) and write F cols 0..7
        const float4* F4 = reinterpret_cast<const float4*>(gF + b * 256);
        const int r1 = (t >> 1) & 1;
#pragma unroll
        for (int k = 0; k < 4; k++) {
            float4 v0 = F4[rr[k] * 4 + 0];
            float4 v1 = F4[rr[k] * 4 + 1];
            float vv[8] = {v0.x, v0.y, v0.z, v0.w, v1.x, v1.y, v1.z, v1.w};
#pragma unroll
            for (int j = 0; j < 2; j++) {
                int cidx = (j + r1) & 1;
                int base = 4 * cidx;
                *reinterpret_cast<u2*>(&S[XO + rr[k] * 16 + 4 * cidx]) =
                    make_ulonglong2(pk2(vv[base], vv[base+1]),
                                    pk2(vv[base+2], vv[base+3]));
            }
        }
    }
    __syncwarp();   // F rows visible

    // ---- phase 8: pc[i][v] = Q[i][v] + dot(tm_i, Frow_v); Q prefetched/vg ----
    {
        const float4* Q4 = reinterpret_cast<const float4*>(gQ + b * 256);
#pragma unroll
        for (int vg = 0; vg < 4; vg++) {
            float4 qv[4];
#pragma unroll
            for (int k = 0; k < 4; k++) qv[k] = Q4[rr[k] * 4 + vg];  // prefetch
            float buf[4][4];
#pragma unroll
            for (int vi = 0; vi < 4; vi++) {
                const float* fr = &S[XO + (vg * 4 + vi) * 16];
                u2 e0 = *reinterpret_cast<const u2*>(fr);
                u2 e1 = *reinterpret_cast<const u2*>(fr + 4);
                u2 e2 = *reinterpret_cast<const u2*>(fr + 8);
                u2 e3 = *reinterpret_cast<const u2*>(fr + 12);
#pragma unroll
                for (int k = 0; k < 4; k++) {
                    ull a0 = ffma2(tp[k][0], e0.x, 0ull);
                    ull a1 = ffma2(tp[k][1], e0.y, 0ull);
                    a0 = ffma2(tp[k][2], e1.x, a0); a1 = ffma2(tp[k][3], e1.y, a1);
                    a0 = ffma2(tp[k][4], e2.x, a0); a1 = ffma2(tp[k][5], e2.y, a1);
                    a0 = ffma2(tp[k][6], e3.x, a0); a1 = ffma2(tp[k][7], e3.y, a1);
                    buf[k][vi] = hsum(add2(a0, a1));
                }
            }
            if (valid) {
#pragma unroll
                for (int k = 0; k < 4; k++) {
                    *reinterpret_cast<float4*>(ocov + b * 256 + rr[k] * 16 + vg * 4) =
                        make_float4(buf[k][0] + qv[k].x, buf[k][1] + qv[k].y,
                                    buf[k][2] + qv[k].z, buf[k][3] + qv[k].w);
                }
            }
        }
    }
}

extern "C" void kernel_launch(void* const* d_in, const int* in_sizes, int n_in,
                              void* d_out, int out_size)
{
    const float* gin   = (const float*)d_in[0];
    const float* gmean = (const float*)d_in[1];
    const float* gcov  = (const float*)d_in[2];
    const float* gH    = (const float*)d_in[3];
    const float* gR    = (const float*)d_in[4];
    const float* gF    = (const float*)d_in[5];
    const float* gQ    = (const float*)d_in[6];

    const int nb = in_sizes[1] / 16;
    float* omean = (float*)d_out;
    float* ocov  = omean + (size_t)nb * 16;

    const int blocks = (nb + GB - 1) / GB;
    kf_step<<<blocks, TPB>>>(gin, gmean, gcov, gH, gR, gF, gQ, omean, ocov, nb);
}

// round 15
// speedup vs baseline: 1.0572x; 1.0572x over previous
#include <cuda_runtime.h>

// Batched Kalman step: B=131072, STATE=16, OBS=8.
// 4 lanes per batch: lane t owns state rows {t,t+4,t+8,t+12}, obs rows {t,t+4}.
// 8 batches per warp, 32 per 128-thread block, 3 blocks/SM (proven 180us cfg).
// NEW vs the 180us build: cov rows are stashed in smem at phase 1 and re-read
// from smem at phase 6 (same-lane RAW, no sync) -- removes the guaranteed
// L2/DRAM-miss cov re-read (-131MB DRAM, -~600cyc exposed stall per warp).
// smem/block grows to 72KB -> dynamic shared memory + FuncSetAttribute.

using ull = unsigned long long;
using u2  = ulonglong2;

__device__ __forceinline__ ull pk2(float lo, float hi) {
    ull r; asm("mov.b64 %0, {%1,%2};" : "=l"(r) : "f"(lo), "f"(hi)); return r;
}
__device__ __forceinline__ ull pk1(float x) {
    ull r; asm("mov.b64 %0, {%1,%1};" : "=l"(r) : "f"(x)); return r;
}
__device__ __forceinline__ void upk(ull v, float& lo, float& hi) {
    asm("mov.b64 {%0,%1}, %2;" : "=f"(lo), "=f"(hi) : "l"(v));
}
__device__ __forceinline__ ull ffma2(ull a, ull b, ull c) {
    ull d; asm("fma.rn.f32x2 %0, %1, %2, %3;" : "=l"(d) : "l"(a), "l"(b), "l"(c)); return d;
}
__device__ __forceinline__ ull add2(ull a, ull b) {
    ull d; asm("add.rn.f32x2 %0, %1, %2;" : "=l"(d) : "l"(a), "l"(b)); return d;
}
__device__ __forceinline__ float hsum(ull a) {
    float lo, hi; upk(a, lo, hi); return lo + hi;
}

static constexpr int GB  = 32;       // batches per block
static constexpr int TPB = 128;      // 4 lanes per batch
// Per-batch smem floats. SB mod 32 = 20 (multiple of 4) -> the 8 warp-groups
// sit on 8 distinct bank-quads for every uniform-offset access.
static constexpr int SB    = 564;
static constexpr int XO    = 0;      // 16x16 region: HT -> WT/SS -> NC -> FT
static constexpr int WTO   = 0;
static constexpr int SSO   = 128;
static constexpr int SMEAN = 256;
static constexpr int SRES  = 272;
static constexpr int SNM   = 280;
static constexpr int CVO   = 296;    // cov stash: 16 rows x 16 floats
static constexpr int SMEM_BYTES = GB * SB * 4;   // 72192 B

__global__ void __launch_bounds__(TPB, 3) kf_step(
    const float* __restrict__ gin,  const float* __restrict__ gmean,
    const float* __restrict__ gcov, const float* __restrict__ gH,
    const float* __restrict__ gR,   const float* __restrict__ gF,
    const float* __restrict__ gQ,
    float* __restrict__ omean, float* __restrict__ ocov, int nb)
{
    extern __shared__ __align__(16) float sm[];
    const int g = threadIdx.x >> 2;
    const int t = threadIdx.x & 3;
    long long b = (long long)blockIdx.x * GB + g;
    const bool valid = (b < nb);
    if (!valid) b = nb - 1;
    float* S = sm + g * SB;
    const int ro = t & 2;   // chunk rotation vs 16t-mod-32 bank aliasing

    int rr[4];
#pragma unroll
    for (int k = 0; k < 4; k++) rr[k] = t + 4 * k;

    // ---- load H rows t,t+4 (packed) + scatter H^T into X cols 0..7; mean ----
    ull hpA[8], hpB[8];
    {
        const float4* H4 = reinterpret_cast<const float4*>(gH + b * 128);
#pragma unroll
        for (int q = 0; q < 4; q++) {
            float4 va = H4[t * 4 + q];
            hpA[2*q] = pk2(va.x, va.y); hpA[2*q+1] = pk2(va.z, va.w);
            S[XO + (4*q+0)*16 + t] = va.x; S[XO + (4*q+1)*16 + t] = va.y;
            S[XO + (4*q+2)*16 + t] = va.z; S[XO + (4*q+3)*16 + t] = va.w;
            float4 vb = H4[(t + 4) * 4 + q];
            hpB[2*q] = pk2(vb.x, vb.y); hpB[2*q+1] = pk2(vb.z, vb.w);
            S[XO + (4*q+0)*16 + t+4] = vb.x; S[XO + (4*q+1)*16 + t+4] = vb.y;
            S[XO + (4*q+2)*16 + t+4] = vb.z; S[XO + (4*q+3)*16 + t+4] = vb.w;
        }
    }
    float m[4];
#pragma unroll
    for (int k = 0; k < 4; k++) { m[k] = gmean[b * 16 + rr[k]]; S[SMEAN + rr[k]] = m[k]; }
    __syncwarp();

    // ---- phase 1: pht[k][o] = sum_s cov[rr[k]][s] * H[o][s]; stash cov -> CV ----
    ull ph[4][4];
#pragma unroll
    for (int k = 0; k < 4; k++)
#pragma unroll
        for (int p = 0; p < 4; p++) ph[k][p] = 0ull;
    float pht[4][8];
    {
        const float4* P4 = reinterpret_cast<const float4*>(gcov + b * 256);
        float c[4][16];
#pragma unroll
        for (int k = 0; k < 4; k++)
#pragma unroll
            for (int q = 0; q < 4; q++) {
                float4 v = P4[rr[k] * 4 + q];
                c[k][4*q] = v.x; c[k][4*q+1] = v.y; c[k][4*q+2] = v.z; c[k][4*q+3] = v.w;
            }
        // stash own cov rows to CV (same-lane RAW with phase 6; no sync needed)
#pragma unroll
        for (int k = 0; k < 4; k++)
#pragma unroll
            for (int jj = 0; jj < 4; jj++) {
                int cq = (jj + ro) & 3;
                *reinterpret_cast<float4*>(&S[CVO + rr[k] * 16 + cq * 4]) =
                    make_float4(c[k][4*cq], c[k][4*cq+1], c[k][4*cq+2], c[k][4*cq+3]);
            }
#pragma unroll
        for (int s = 0; s < 16; s++) {
            u2 hA = *reinterpret_cast<const u2*>(&S[XO + s * 16]);
            u2 hB = *reinterpret_cast<const u2*>(&S[XO + s * 16 + 4]);
#pragma unroll
            for (int k = 0; k < 4; k++) {
                ull cs = pk1(c[k][s]);
                ph[k][0] = ffma2(hA.x, cs, ph[k][0]); ph[k][1] = ffma2(hA.y, cs, ph[k][1]);
                ph[k][2] = ffma2(hB.x, cs, ph[k][2]); ph[k][3] = ffma2(hB.y, cs, ph[k][3]);
            }
        }
#pragma unroll
        for (int k = 0; k < 4; k++)
#pragma unroll
            for (int p = 0; p < 4; p++) upk(ph[k][p], pht[k][2*p], pht[k][2*p+1]);
    }
    __syncwarp();   // all HT reads done before WT overlays X rows 0..7
#pragma unroll
    for (int o = 0; o < 8; o++)
#pragma unroll
        for (int k = 0; k < 4; k++) S[WTO + o * 16 + rr[k]] = pht[k][o];
    __syncwarp();

    // ---- phase 2: S rows t, t+4 : S[i][j] = dot(Hrow_i, WTrow_j) + R[i][j] ----
    {
        float4 Ra0 = *reinterpret_cast<const float4*>(gR + b * 64 + t * 8);
        float4 Ra1 = *reinterpret_cast<const float4*>(gR + b * 64 + t * 8 + 4);
        float4 Rb0 = *reinterpret_cast<const float4*>(gR + b * 64 + (t + 4) * 8);
        float4 Rb1 = *reinterpret_cast<const float4*>(gR + b * 64 + (t + 4) * 8 + 4);
        float rA[8] = {Ra0.x,Ra0.y,Ra0.z,Ra0.w, Ra1.x,Ra1.y,Ra1.z,Ra1.w};
        float rB[8] = {Rb0.x,Rb0.y,Rb0.z,Rb0.w, Rb1.x,Rb1.y,Rb1.z,Rb1.w};
        float svA[8], svB[8];
#pragma unroll
        for (int j = 0; j < 8; j++) {
            const float* wr = &S[WTO + j * 16];
            u2 w0 = *reinterpret_cast<const u2*>(wr);
            u2 w1 = *reinterpret_cast<const u2*>(wr + 4);
            u2 w2 = *reinterpret_cast<const u2*>(wr + 8);
            u2 w3 = *reinterpret_cast<const u2*>(wr + 12);
            ull a0 = ffma2(hpA[0], w0.x, 0ull), a1 = ffma2(hpA[1], w0.y, 0ull);
            a0 = ffma2(hpA[2], w1.x, a0); a1 = ffma2(hpA[3], w1.y, a1);
            a0 = ffma2(hpA[4], w2.x, a0); a1 = ffma2(hpA[5], w2.y, a1);
            a0 = ffma2(hpA[6], w3.x, a0); a1 = ffma2(hpA[7], w3.y, a1);
            svA[j] = rA[j] + hsum(add2(a0, a1));
            ull b0 = ffma2(hpB[0], w0.x, 0ull), b1 = ffma2(hpB[1], w0.y, 0ull);
            b0 = ffma2(hpB[2], w1.x, b0); b1 = ffma2(hpB[3], w1.y, b1);
            b0 = ffma2(hpB[4], w2.x, b0); b1 = ffma2(hpB[5], w2.y, b1);
            b0 = ffma2(hpB[6], w3.x, b0); b1 = ffma2(hpB[7], w3.y, b1);
            svB[j] = rB[j] + hsum(add2(b0, b1));
        }
        float4* sa = reinterpret_cast<float4*>(&S[SSO + t * 8]);
        sa[0] = make_float4(svA[0], svA[1], svA[2], svA[3]);
        sa[1] = make_float4(svA[4], svA[5], svA[6], svA[7]);
        float4* sb = reinterpret_cast<float4*>(&S[SSO + (t + 4) * 8]);
        sb[0] = make_float4(svB[0], svB[1], svB[2], svB[3]);
        sb[1] = make_float4(svB[4], svB[5], svB[6], svB[7]);
    }
    __syncwarp();

    // ---- phase 3: redundant per-lane Cholesky of S; 4 RHS solves -> K rows ----
    float L[28], dinv[8];
#pragma unroll
    for (int j = 0; j < 8; j++) {
        float d = S[SSO + j * 8 + j];
#pragma unroll
        for (int k2 = 0; k2 < j; k2++) d -= L[j*(j-1)/2 + k2] * L[j*(j-1)/2 + k2];
        float inv = rsqrtf(d);
        dinv[j] = inv;
#pragma unroll
        for (int i2 = j + 1; i2 < 8; i2++) {
            float e = S[SSO + i2 * 8 + j];
#pragma unroll
            for (int k2 = 0; k2 < j; k2++) e -= L[i2*(i2-1)/2 + k2] * L[j*(j-1)/2 + k2];
            L[i2*(i2-1)/2 + j] = e * inv;
        }
    }
    float K[4][8];
#pragma unroll
    for (int k = 0; k < 4; k++) {
        float y[8];
#pragma unroll
        for (int j = 0; j < 8; j++) {
            float e = pht[k][j];
#pragma unroll
            for (int k2 = 0; k2 < j; k2++) e -= L[j*(j-1)/2 + k2] * y[k2];
            y[j] = e * dinv[j];
        }
#pragma unroll
        for (int j = 7; j >= 0; j--) {
            float e = y[j];
#pragma unroll
            for (int k2 = j + 1; k2 < 8; k2++) e -= L[k2*(k2-1)/2 + j] * K[k][k2];
            K[k][j] = e * dinv[j];
        }
    }

    // ---- resid rows t, t+4 ----
    {
        float eA = gin[b * 8 + t], eB = gin[b * 8 + t + 4];
        const float* mp = &S[SMEAN];
        u2 q0 = *reinterpret_cast<const u2*>(mp);
        u2 q1 = *reinterpret_cast<const u2*>(mp + 4);
        u2 q2 = *reinterpret_cast<const u2*>(mp + 8);
        u2 q3 = *reinterpret_cast<const u2*>(mp + 12);
        ull a0 = ffma2(hpA[0], q0.x, 0ull), a1 = ffma2(hpA[1], q0.y, 0ull);
        a0 = ffma2(hpA[2], q1.x, a0); a1 = ffma2(hpA[3], q1.y, a1);
        a0 = ffma2(hpA[4], q2.x, a0); a1 = ffma2(hpA[5], q2.y, a1);
        a0 = ffma2(hpA[6], q3.x, a0); a1 = ffma2(hpA[7], q3.y, a1);
        S[SRES + t] = eA - hsum(add2(a0, a1));
        ull b0 = ffma2(hpB[0], q0.x, 0ull), b1 = ffma2(hpB[1], q0.y, 0ull);
        b0 = ffma2(hpB[2], q1.x, b0); b1 = ffma2(hpB[3], q1.y, b1);
        b0 = ffma2(hpB[4], q2.x, b0); b1 = ffma2(hpB[5], q2.y, b1);
        b0 = ffma2(hpB[6], q3.x, b0); b1 = ffma2(hpB[7], q3.y, b1);
        S[SRES + t + 4] = eB - hsum(add2(b0, b1));
    }
    __syncwarp();

    // ---- new_mean rows -> SNM ----
    {
        u2 e0 = *reinterpret_cast<const u2*>(&S[SRES]);
        u2 e1 = *reinterpret_cast<const u2*>(&S[SRES + 4]);
#pragma unroll
        for (int k = 0; k < 4; k++) {
            ull a0 = ffma2(pk2(K[k][0], K[k][1]), e0.x, 0ull);
            ull a1 = ffma2(pk2(K[k][2], K[k][3]), e0.y, 0ull);
            a0 = ffma2(pk2(K[k][4], K[k][5]), e1.x, a0);
            a1 = ffma2(pk2(K[k][6], K[k][7]), e1.y, a1);
            S[SNM + rr[k]] = m[k] + hsum(add2(a0, a1));
        }
    }

    // ---- phase 6: NC rows = cov(from CV smem stash) - K.W ----
    ull nc[4][8];
#pragma unroll
    for (int k = 0; k < 4; k++)
#pragma unroll
        for (int jj = 0; jj < 4; jj++) {
            int cq = (jj + ro) & 3;
            float4 v = *reinterpret_cast<const float4*>(&S[CVO + rr[k] * 16 + cq * 4]);
            nc[k][2*cq] = pk2(v.x, v.y); nc[k][2*cq+1] = pk2(v.z, v.w);
        }
#pragma unroll
    for (int o = 0; o < 8; o++) {
        const float* wr = &S[WTO + o * 16];
        u2 w0 = *reinterpret_cast<const u2*>(wr);
        u2 w1 = *reinterpret_cast<const u2*>(wr + 4);
        u2 w2 = *reinterpret_cast<const u2*>(wr + 8);
        u2 w3 = *reinterpret_cast<const u2*>(wr + 12);
#pragma unroll
        for (int k = 0; k < 4; k++) {
            ull nk = pk1(-K[k][o]);
            nc[k][0] = ffma2(w0.x, nk, nc[k][0]); nc[k][1] = ffma2(w0.y, nk, nc[k][1]);
            nc[k][2] = ffma2(w1.x, nk, nc[k][2]); nc[k][3] = ffma2(w1.y, nk, nc[k][3]);
            nc[k][4] = ffma2(w2.x, nk, nc[k][4]); nc[k][5] = ffma2(w2.y, nk, nc[k][5]);
            nc[k][6] = ffma2(w3.x, nk, nc[k][6]); nc[k][7] = ffma2(w3.y, nk, nc[k][7]);
        }
    }
    __syncwarp();   // all WT reads + SNM writes complete before NC overlays X
    {
#pragma unroll
        for (int k = 0; k < 4; k++) {
            u2* nr = reinterpret_cast<u2*>(&S[XO + rr[k] * 16]);
#pragma unroll
            for (int jj = 0; jj < 4; jj++) {
                int cj = (jj + ro) & 3;
                nr[cj] = make_ulonglong2(nc[k][2*cj], nc[k][2*cj+1]);
            }
        }
    }

    // ---- load F rows; pred_mean (SNM outside X, safe) ----
    float f[4][16];
    {
        const float4* F4 = reinterpret_cast<const float4*>(gF + b * 256);
#pragma unroll
        for (int k = 0; k < 4; k++)
#pragma unroll
            for (int q = 0; q < 4; q++) {
                float4 v = F4[rr[k] * 4 + q];
                f[k][4*q] = v.x; f[k][4*q+1] = v.y; f[k][4*q+2] = v.z; f[k][4*q+3] = v.w;
            }
    }
    {
        const float* np = &S[SNM];
        u2 n0 = *reinterpret_cast<const u2*>(np);
        u2 n1 = *reinterpret_cast<const u2*>(np + 4);
        u2 n2 = *reinterpret_cast<const u2*>(np + 8);
        u2 n3 = *reinterpret_cast<const u2*>(np + 12);
#pragma unroll
        for (int k = 0; k < 4; k++) {
            ull a0 = ffma2(pk2(f[k][0],  f[k][1]),  n0.x, 0ull);
            ull a1 = ffma2(pk2(f[k][2],  f[k][3]),  n0.y, 0ull);
            a0 = ffma2(pk2(f[k][4],  f[k][5]),  n1.x, a0);
            a1 = ffma2(pk2(f[k][6],  f[k][7]),  n1.y, a1);
            a0 = ffma2(pk2(f[k][8],  f[k][9]),  n2.x, a0);
            a1 = ffma2(pk2(f[k][10], f[k][11]), n2.y, a1);
            a0 = ffma2(pk2(f[k][12], f[k][13]), n3.x, a0);
            a1 = ffma2(pk2(f[k][14], f[k][15]), n3.y, a1);
            if (valid) omean[b * 16 + rr[k]] = hsum(add2(a0, a1));
        }
    }
    __syncwarp();   // NC writes visible

    // ---- phase 7: tp[k][p] packs tm[k][2p],tm[k][2p+1]; tm = F.NC row ----
    ull tp[4][8];
#pragma unroll
    for (int k = 0; k < 4; k++)
#pragma unroll
        for (int p = 0; p < 8; p++) tp[k][p] = 0ull;
#pragma unroll
    for (int u = 0; u < 16; u++) {
        const float* nr = &S[XO + u * 16];
        u2 n0 = *reinterpret_cast<const u2*>(nr);
        u2 n1 = *reinterpret_cast<const u2*>(nr + 4);
        u2 n2 = *reinterpret_cast<const u2*>(nr + 8);
        u2 n3 = *reinterpret_cast<const u2*>(nr + 12);
#pragma unroll
        for (int k = 0; k < 4; k++) {
            ull fu = pk1(f[k][u]);
            tp[k][0] = ffma2(n0.x, fu, tp[k][0]); tp[k][1] = ffma2(n0.y, fu, tp[k][1]);
            tp[k][2] = ffma2(n1.x, fu, tp[k][2]); tp[k][3] = ffma2(n1.y, fu, tp[k][3]);
            tp[k][4] = ffma2(n2.x, fu, tp[k][4]); tp[k][5] = ffma2(n2.y, fu, tp[k][5]);
            tp[k][6] = ffma2(n3.x, fu, tp[k][6]); tp[k][7] = ffma2(n3.y, fu, tp[k][7]);
        }
    }
    __syncwarp();   // all NC reads done before FT overlays X

    // ---- F^T into X from registers (f dies here) ----
#pragma unroll
    for (int u = 0; u < 16; u++)
#pragma unroll
        for (int k = 0; k < 4; k++) S[XO + u * 16 + rr[k]] = f[k][u];
    __syncwarp();

    // ---- phase 8: pred_cov rows = Q + sum_u tm[k][u] * F^T[u][:] ----
    // tm[k][u] extracted on the fly from tp[k][u>>1] (no tm array).
    ull pc[4][8];
    {
        const float4* Q4 = reinterpret_cast<const float4*>(gQ + b * 256);
#pragma unroll
        for (int k = 0; k < 4; k++)
#pragma unroll
            for (int q = 0; q < 4; q++) {
                float4 v = Q4[rr[k] * 4 + q];
                pc[k][2*q] = pk2(v.x, v.y); pc[k][2*q+1] = pk2(v.z, v.w);
            }
    }
#pragma unroll
    for (int p = 0; p < 8; p++) {
#pragma unroll
        for (int half = 0; half < 2; half++) {
            const int u = 2 * p + half;
            const float* fr = &S[XO + u * 16];
            u2 e0 = *reinterpret_cast<const u2*>(fr);
            u2 e1 = *reinterpret_cast<const u2*>(fr + 4);
            u2 e2 = *reinterpret_cast<const u2*>(fr + 8);
            u2 e3 = *reinterpret_cast<const u2*>(fr + 12);
#pragma unroll
            for (int k = 0; k < 4; k++) {
                float lo, hi; upk(tp[k][p], lo, hi);
                ull tu = pk1(half ? hi : lo);
                pc[k][0] = ffma2(e0.x, tu, pc[k][0]); pc[k][1] = ffma2(e0.y, tu, pc[k][1]);
                pc[k][2] = ffma2(e1.x, tu, pc[k][2]); pc[k][3] = ffma2(e1.y, tu, pc[k][3]);
                pc[k][4] = ffma2(e2.x, tu, pc[k][4]); pc[k][5] = ffma2(e2.y, tu, pc[k][5]);
                pc[k][6] = ffma2(e3.x, tu, pc[k][6]); pc[k][7] = ffma2(e3.y, tu, pc[k][7]);
            }
        }
    }

    if (valid) {
#pragma unroll
        for (int k = 0; k < 4; k++) {
            float v[16];
#pragma unroll
            for (int p = 0; p < 8; p++) upk(pc[k][p], v[2*p], v[2*p+1]);
            float4* od = reinterpret_cast<float4*>(ocov + b * 256 + rr[k] * 16);
            od[0] = make_float4(v[0],  v[1],  v[2],  v[3]);
            od[1] = make_float4(v[4],  v[5],  v[6],  v[7]);
            od[2] = make_float4(v[8],  v[9],  v[10], v[11]);
            od[3] = make_float4(v[12], v[13], v[14], v[15]);
        }
    }
}

extern "C" void kernel_launch(void* const* d_in, const int* in_sizes, int n_in,
                              void* d_out, int out_size)
{
    const float* gin   = (const float*)d_in[0];
    const float* gmean = (const float*)d_in[1];
    const float* gcov  = (const float*)d_in[2];
    const float* gH    = (const float*)d_in[3];
    const float* gR    = (const float*)d_in[4];
    const float* gF    = (const float*)d_in[5];
    const float* gQ    = (const float*)d_in[6];

    const int nb = in_sizes[1] / 16;
    float* omean = (float*)d_out;
    float* ocov  = omean + (size_t)nb * 16;

    // 72KB dynamic smem > 48KB default: raise the limit (idempotent, not a
    // stream op -- safe under graph capture).
    cudaFuncSetAttribute(kf_step, cudaFuncAttributeMaxDynamicSharedMemorySize,
                         SMEM_BYTES);

    const int blocks = (nb + GB - 1) / GB;
    kf_step<<<blocks, TPB, SMEM_BYTES>>>(gin, gmean, gcov, gH, gR, gF, gQ,
                                         omean, ocov, nb);
}

// round 16
// speedup vs baseline: 1.5286x; 1.4458x over previous
#include <cuda_runtime.h>

// Batched Kalman step: B=131072, STATE=16, OBS=8.
// 4 lanes per batch: lane t owns state rows {t,t+4,t+8,t+12}, obs rows {t,t+4}.
// 8 batches per warp, 32 per 128-thread block, 3 blocks/SM (proven 180us cfg).
// R16 = R11 + latency micro-fixes, same register class:
//  - gin loaded at kernel top (hide DRAM latency across phases 1-2)
//  - resid before Cholesky (packed-H regs die earlier; peak unchanged)
//  - F global loads issued before the NC smem stores (overlap miss latency).

using ull = unsigned long long;
using u2  = ulonglong2;

__device__ __forceinline__ ull pk2(float lo, float hi) {
    ull r; asm("mov.b64 %0, {%1,%2};" : "=l"(r) : "f"(lo), "f"(hi)); return r;
}
__device__ __forceinline__ ull pk1(float x) {
    ull r; asm("mov.b64 %0, {%1,%1};" : "=l"(r) : "f"(x)); return r;
}
__device__ __forceinline__ void upk(ull v, float& lo, float& hi) {
    asm("mov.b64 {%0,%1}, %2;" : "=f"(lo), "=f"(hi) : "l"(v));
}
__device__ __forceinline__ ull ffma2(ull a, ull b, ull c) {
    ull d; asm("fma.rn.f32x2 %0, %1, %2, %3;" : "=l"(d) : "l"(a), "l"(b), "l"(c)); return d;
}
__device__ __forceinline__ ull add2(ull a, ull b) {
    ull d; asm("add.rn.f32x2 %0, %1, %2;" : "=l"(d) : "l"(a), "l"(b)); return d;
}
__device__ __forceinline__ float hsum(ull a) {
    float lo, hi; upk(a, lo, hi); return lo + hi;
}

static constexpr int GB  = 32;       // batches per block
static constexpr int TPB = 128;      // 4 lanes per batch
static constexpr int SB    = 324;    // per-batch smem floats; ≡4 mod 32 banks
static constexpr int XO    = 0;      // 16x16 region: HT -> WT/SS -> NC -> FT
static constexpr int WTO   = 0;
static constexpr int SSO   = 128;
static constexpr int SMEAN = 256;
static constexpr int SRES  = 272;
static constexpr int SNM   = 280;

__global__ void __launch_bounds__(TPB, 3) kf_step(
    const float* __restrict__ gin,  const float* __restrict__ gmean,
    const float* __restrict__ gcov, const float* __restrict__ gH,
    const float* __restrict__ gR,   const float* __restrict__ gF,
    const float* __restrict__ gQ,
    float* __restrict__ omean, float* __restrict__ ocov, int nb)
{
    __shared__ __align__(16) float sm[GB * SB];
    const int g = threadIdx.x >> 2;
    const int t = threadIdx.x & 3;
    long long b = (long long)blockIdx.x * GB + g;
    const bool valid = (b < nb);
    if (!valid) b = nb - 1;
    float* S = sm + g * SB;

    int rr[4];
#pragma unroll
    for (int k = 0; k < 4; k++) rr[k] = t + 4 * k;

    // ---- early loads: gin (consumed at resid, latency hidden) ----
    const float giA = gin[b * 8 + t];
    const float giB = gin[b * 8 + t + 4];

    // ---- load H rows t,t+4 (packed) + scatter H^T into X cols 0..7; mean ----
    ull hpA[8], hpB[8];
    {
        const float4* H4 = reinterpret_cast<const float4*>(gH + b * 128);
#pragma unroll
        for (int q = 0; q < 4; q++) {
            float4 va = H4[t * 4 + q];
            hpA[2*q] = pk2(va.x, va.y); hpA[2*q+1] = pk2(va.z, va.w);
            S[XO + (4*q+0)*16 + t] = va.x; S[XO + (4*q+1)*16 + t] = va.y;
            S[XO + (4*q+2)*16 + t] = va.z; S[XO + (4*q+3)*16 + t] = va.w;
            float4 vb = H4[(t + 4) * 4 + q];
            hpB[2*q] = pk2(vb.x, vb.y); hpB[2*q+1] = pk2(vb.z, vb.w);
            S[XO + (4*q+0)*16 + t+4] = vb.x; S[XO + (4*q+1)*16 + t+4] = vb.y;
            S[XO + (4*q+2)*16 + t+4] = vb.z; S[XO + (4*q+3)*16 + t+4] = vb.w;
        }
    }
    float m[4];
#pragma unroll
    for (int k = 0; k < 4; k++) { m[k] = gmean[b * 16 + rr[k]]; S[SMEAN + rr[k]] = m[k]; }
    __syncwarp();

    // ---- phase 1: pht[k][o] = sum_s cov[rr[k]][s] * H[o][s] ----
    ull ph[4][4];
#pragma unroll
    for (int k = 0; k < 4; k++)
#pragma unroll
        for (int p = 0; p < 4; p++) ph[k][p] = 0ull;
    float pht[4][8];
    {
        const float4* P4 = reinterpret_cast<const float4*>(gcov + b * 256);
        float c[4][16];
#pragma unroll
        for (int k = 0; k < 4; k++)
#pragma unroll
            for (int q = 0; q < 4; q++) {
                float4 v = P4[rr[k] * 4 + q];
                c[k][4*q] = v.x; c[k][4*q+1] = v.y; c[k][4*q+2] = v.z; c[k][4*q+3] = v.w;
            }
#pragma unroll
        for (int s = 0; s < 16; s++) {
            u2 hA = *reinterpret_cast<const u2*>(&S[XO + s * 16]);
            u2 hB = *reinterpret_cast<const u2*>(&S[XO + s * 16 + 4]);
#pragma unroll
            for (int k = 0; k < 4; k++) {
                ull cs = pk1(c[k][s]);
                ph[k][0] = ffma2(hA.x, cs, ph[k][0]); ph[k][1] = ffma2(hA.y, cs, ph[k][1]);
                ph[k][2] = ffma2(hB.x, cs, ph[k][2]); ph[k][3] = ffma2(hB.y, cs, ph[k][3]);
            }
        }
#pragma unroll
        for (int k = 0; k < 4; k++)
#pragma unroll
            for (int p = 0; p < 4; p++) upk(ph[k][p], pht[k][2*p], pht[k][2*p+1]);
    }
    __syncwarp();   // all HT reads done before WT overlays X rows 0..7
#pragma unroll
    for (int o = 0; o < 8; o++)
#pragma unroll
        for (int k = 0; k < 4; k++) S[WTO + o * 16 + rr[k]] = pht[k][o];
    __syncwarp();

    // ---- phase 2: S rows t, t+4 : S[i][j] = dot(Hrow_i, WTrow_j) + R[i][j] ----
    {
        float4 Ra0 = *reinterpret_cast<const float4*>(gR + b * 64 + t * 8);
        float4 Ra1 = *reinterpret_cast<const float4*>(gR + b * 64 + t * 8 + 4);
        float4 Rb0 = *reinterpret_cast<const float4*>(gR + b * 64 + (t + 4) * 8);
        float4 Rb1 = *reinterpret_cast<const float4*>(gR + b * 64 + (t + 4) * 8 + 4);
        float rA[8] = {Ra0.x,Ra0.y,Ra0.z,Ra0.w, Ra1.x,Ra1.y,Ra1.z,Ra1.w};
        float rB[8] = {Rb0.x,Rb0.y,Rb0.z,Rb0.w, Rb1.x,Rb1.y,Rb1.z,Rb1.w};
        float svA[8], svB[8];
#pragma unroll
        for (int j = 0; j < 8; j++) {
            const float* wr = &S[WTO + j * 16];
            u2 w0 = *reinterpret_cast<const u2*>(wr);
            u2 w1 = *reinterpret_cast<const u2*>(wr + 4);
            u2 w2 = *reinterpret_cast<const u2*>(wr + 8);
            u2 w3 = *reinterpret_cast<const u2*>(wr + 12);
            ull a0 = ffma2(hpA[0], w0.x, 0ull), a1 = ffma2(hpA[1], w0.y, 0ull);
            a0 = ffma2(hpA[2], w1.x, a0); a1 = ffma2(hpA[3], w1.y, a1);
            a0 = ffma2(hpA[4], w2.x, a0); a1 = ffma2(hpA[5], w2.y, a1);
            a0 = ffma2(hpA[6], w3.x, a0); a1 = ffma2(hpA[7], w3.y, a1);
            svA[j] = rA[j] + hsum(add2(a0, a1));
            ull b0 = ffma2(hpB[0], w0.x, 0ull), b1 = ffma2(hpB[1], w0.y, 0ull);
            b0 = ffma2(hpB[2], w1.x, b0); b1 = ffma2(hpB[3], w1.y, b1);
            b0 = ffma2(hpB[4], w2.x, b0); b1 = ffma2(hpB[5], w2.y, b1);
            b0 = ffma2(hpB[6], w3.x, b0); b1 = ffma2(hpB[7], w3.y, b1);
            svB[j] = rB[j] + hsum(add2(b0, b1));
        }
        float4* sa = reinterpret_cast<float4*>(&S[SSO + t * 8]);
        sa[0] = make_float4(svA[0], svA[1], svA[2], svA[3]);
        sa[1] = make_float4(svA[4], svA[5], svA[6], svA[7]);
        float4* sb = reinterpret_cast<float4*>(&S[SSO + (t + 4) * 8]);
        sb[0] = make_float4(svB[0], svB[1], svB[2], svB[3]);
        sb[1] = make_float4(svB[4], svB[5], svB[6], svB[7]);
    }

    // ---- resid rows t, t+4 (before Cholesky: hpA/hpB die here) ----
    {
        const float* mp = &S[SMEAN];
        u2 q0 = *reinterpret_cast<const u2*>(mp);
        u2 q1 = *reinterpret_cast<const u2*>(mp + 4);
        u2 q2 = *reinterpret_cast<const u2*>(mp + 8);
        u2 q3 = *reinterpret_cast<const u2*>(mp + 12);
        ull a0 = ffma2(hpA[0], q0.x, 0ull), a1 = ffma2(hpA[1], q0.y, 0ull);
        a0 = ffma2(hpA[2], q1.x, a0); a1 = ffma2(hpA[3], q1.y, a1);
        a0 = ffma2(hpA[4], q2.x, a0); a1 = ffma2(hpA[5], q2.y, a1);
        a0 = ffma2(hpA[6], q3.x, a0); a1 = ffma2(hpA[7], q3.y, a1);
        S[SRES + t] = giA - hsum(add2(a0, a1));
        ull b0 = ffma2(hpB[0], q0.x, 0ull), b1 = ffma2(hpB[1], q0.y, 0ull);
        b0 = ffma2(hpB[2], q1.x, b0); b1 = ffma2(hpB[3], q1.y, b1);
        b0 = ffma2(hpB[4], q2.x, b0); b1 = ffma2(hpB[5], q2.y, b1);
        b0 = ffma2(hpB[6], q3.x, b0); b1 = ffma2(hpB[7], q3.y, b1);
        S[SRES + t + 4] = giB - hsum(add2(b0, b1));
    }
    __syncwarp();   // SS + SRES visible

    // ---- phase 3: redundant per-lane Cholesky of S; 4 RHS solves -> K rows ----
    float L[28], dinv[8];
#pragma unroll
    for (int j = 0; j < 8; j++) {
        float d = S[SSO + j * 8 + j];
#pragma unroll
        for (int k2 = 0; k2 < j; k2++) d -= L[j*(j-1)/2 + k2] * L[j*(j-1)/2 + k2];
        float inv = rsqrtf(d);
        dinv[j] = inv;
#pragma unroll
        for (int i2 = j + 1; i2 < 8; i2++) {
            float e = S[SSO + i2 * 8 + j];
#pragma unroll
            for (int k2 = 0; k2 < j; k2++) e -= L[i2*(i2-1)/2 + k2] * L[j*(j-1)/2 + k2];
            L[i2*(i2-1)/2 + j] = e * inv;
        }
    }
    float K[4][8];
#pragma unroll
    for (int k = 0; k < 4; k++) {
        float y[8];
#pragma unroll
        for (int j = 0; j < 8; j++) {
            float e = pht[k][j];
#pragma unroll
            for (int k2 = 0; k2 < j; k2++) e -= L[j*(j-1)/2 + k2] * y[k2];
            y[j] = e * dinv[j];
        }
#pragma unroll
        for (int j = 7; j >= 0; j--) {
            float e = y[j];
#pragma unroll
            for (int k2 = j + 1; k2 < 8; k2++) e -= L[k2*(k2-1)/2 + j] * K[k][k2];
            K[k][j] = e * dinv[j];
        }
    }

    // ---- new_mean rows -> SNM ----
    {
        u2 e0 = *reinterpret_cast<const u2*>(&S[SRES]);
        u2 e1 = *reinterpret_cast<const u2*>(&S[SRES + 4]);
#pragma unroll
        for (int k = 0; k < 4; k++) {
            ull a0 = ffma2(pk2(K[k][0], K[k][1]), e0.x, 0ull);
            ull a1 = ffma2(pk2(K[k][2], K[k][3]), e0.y, 0ull);
            a0 = ffma2(pk2(K[k][4], K[k][5]), e1.x, a0);
            a1 = ffma2(pk2(K[k][6], K[k][7]), e1.y, a1);
            S[SNM + rr[k]] = m[k] + hsum(add2(a0, a1));
        }
    }

    // ---- phase 6: NC rows = cov - K.W  (cov re-loaded, L2-hot) ----
    ull nc[4][8];
    {
        const float4* P4 = reinterpret_cast<const float4*>(gcov + b * 256);
#pragma unroll
        for (int k = 0; k < 4; k++)
#pragma unroll
            for (int q = 0; q < 4; q++) {
                float4 v = P4[rr[k] * 4 + q];
                nc[k][2*q] = pk2(v.x, v.y); nc[k][2*q+1] = pk2(v.z, v.w);
            }
    }
#pragma unroll
    for (int o = 0; o < 8; o++) {
        const float* wr = &S[WTO + o * 16];
        u2 w0 = *reinterpret_cast<const u2*>(wr);
        u2 w1 = *reinterpret_cast<const u2*>(wr + 4);
        u2 w2 = *reinterpret_cast<const u2*>(wr + 8);
        u2 w3 = *reinterpret_cast<const u2*>(wr + 12);
#pragma unroll
        for (int k = 0; k < 4; k++) {
            ull nk = pk1(-K[k][o]);
            nc[k][0] = ffma2(w0.x, nk, nc[k][0]); nc[k][1] = ffma2(w0.y, nk, nc[k][1]);
            nc[k][2] = ffma2(w1.x, nk, nc[k][2]); nc[k][3] = ffma2(w1.y, nk, nc[k][3]);
            nc[k][4] = ffma2(w2.x, nk, nc[k][4]); nc[k][5] = ffma2(w2.y, nk, nc[k][5]);
            nc[k][6] = ffma2(w3.x, nk, nc[k][6]); nc[k][7] = ffma2(w3.y, nk, nc[k][7]);
        }
    }

    // ---- F loads issued NOW (independent): latency overlaps NC store+syncs ----
    float f[4][16];
    {
        const float4* F4 = reinterpret_cast<const float4*>(gF + b * 256);
#pragma unroll
        for (int k = 0; k < 4; k++)
#pragma unroll
            for (int q = 0; q < 4; q++) {
                float4 v = F4[rr[k] * 4 + q];
                f[k][4*q] = v.x; f[k][4*q+1] = v.y; f[k][4*q+2] = v.z; f[k][4*q+3] = v.w;
            }
    }

    __syncwarp();   // all WT reads + SNM writes complete before NC overlays X
    {
        const int ro = t & 2;   // chunk rotation vs 16t-mod-32 bank aliasing
#pragma unroll
        for (int k = 0; k < 4; k++) {
            u2* nr = reinterpret_cast<u2*>(&S[XO + rr[k] * 16]);
#pragma unroll
            for (int jj = 0; jj < 4; jj++) {
                int cj = (jj + ro) & 3;
                nr[cj] = make_ulonglong2(nc[k][2*cj], nc[k][2*cj+1]);
            }
        }
    }

    // ---- pred_mean (SNM outside X, safe) ----
    {
        const float* np = &S[SNM];
        u2 n0 = *reinterpret_cast<const u2*>(np);
        u2 n1 = *reinterpret_cast<const u2*>(np + 4);
        u2 n2 = *reinterpret_cast<const u2*>(np + 8);
        u2 n3 = *reinterpret_cast<const u2*>(np + 12);
#pragma unroll
        for (int k = 0; k < 4; k++) {
            ull a0 = ffma2(pk2(f[k][0],  f[k][1]),  n0.x, 0ull);
            ull a1 = ffma2(pk2(f[k][2],  f[k][3]),  n0.y, 0ull);
            a0 = ffma2(pk2(f[k][4],  f[k][5]),  n1.x, a0);
            a1 = ffma2(pk2(f[k][6],  f[k][7]),  n1.y, a1);
            a0 = ffma2(pk2(f[k][8],  f[k][9]),  n2.x, a0);
            a1 = ffma2(pk2(f[k][10], f[k][11]), n2.y, a1);
            a0 = ffma2(pk2(f[k][12], f[k][13]), n3.x, a0);
            a1 = ffma2(pk2(f[k][14], f[k][15]), n3.y, a1);
            if (valid) omean[b * 16 + rr[k]] = hsum(add2(a0, a1));
        }
    }
    __syncwarp();   // NC writes visible

    // ---- phase 7: tp[k][p] packs tm[k][2p],tm[k][2p+1]; tm = F.NC row ----
    ull tp[4][8];
#pragma unroll
    for (int k = 0; k < 4; k++)
#pragma unroll
        for (int p = 0; p < 8; p++) tp[k][p] = 0ull;
#pragma unroll
    for (int u = 0; u < 16; u++) {
        const float* nr = &S[XO + u * 16];
        u2 n0 = *reinterpret_cast<const u2*>(nr);
        u2 n1 = *reinterpret_cast<const u2*>(nr + 4);
        u2 n2 = *reinterpret_cast<const u2*>(nr + 8);
        u2 n3 = *reinterpret_cast<const u2*>(nr + 12);
#pragma unroll
        for (int k = 0; k < 4; k++) {
            ull fu = pk1(f[k][u]);
            tp[k][0] = ffma2(n0.x, fu, tp[k][0]); tp[k][1] = ffma2(n0.y, fu, tp[k][1]);
            tp[k][2] = ffma2(n1.x, fu, tp[k][2]); tp[k][3] = ffma2(n1.y, fu, tp[k][3]);
            tp[k][4] = ffma2(n2.x, fu, tp[k][4]); tp[k][5] = ffma2(n2.y, fu, tp[k][5]);
            tp[k][6] = ffma2(n3.x, fu, tp[k][6]); tp[k][7] = ffma2(n3.y, fu, tp[k][7]);
        }
    }
    __syncwarp();   // all NC reads done before FT overlays X

    // ---- F^T into X from registers (f dies here) ----
#pragma unroll
    for (int u = 0; u < 16; u++)
#pragma unroll
        for (int k = 0; k < 4; k++) S[XO + u * 16 + rr[k]] = f[k][u];
    __syncwarp();

    // ---- phase 8: pred_cov rows = Q + sum_u tm[k][u] * F^T[u][:] ----
    // tm[k][u] extracted on the fly from tp[k][u>>1] (no tm array).
    ull pc[4][8];
    {
        const float4* Q4 = reinterpret_cast<const float4*>(gQ + b * 256);
#pragma unroll
        for (int k = 0; k < 4; k++)
#pragma unroll
            for (int q = 0; q < 4; q++) {
                float4 v = Q4[rr[k] * 4 + q];
                pc[k][2*q] = pk2(v.x, v.y); pc[k][2*q+1] = pk2(v.z, v.w);
            }
    }
#pragma unroll
    for (int p = 0; p < 8; p++) {
#pragma unroll
        for (int half = 0; half < 2; half++) {
            const int u = 2 * p + half;
            const float* fr = &S[XO + u * 16];
            u2 e0 = *reinterpret_cast<const u2*>(fr);
            u2 e1 = *reinterpret_cast<const u2*>(fr + 4);
            u2 e2 = *reinterpret_cast<const u2*>(fr + 8);
            u2 e3 = *reinterpret_cast<const u2*>(fr + 12);
#pragma unroll
            for (int k = 0; k < 4; k++) {
                float lo, hi; upk(tp[k][p], lo, hi);
                ull tu = pk1(half ? hi : lo);
                pc[k][0] = ffma2(e0.x, tu, pc[k][0]); pc[k][1] = ffma2(e0.y, tu, pc[k][1]);
                pc[k][2] = ffma2(e1.x, tu, pc[k][2]); pc[k][3] = ffma2(e1.y, tu, pc[k][3]);
                pc[k][4] = ffma2(e2.x, tu, pc[k][4]); pc[k][5] = ffma2(e2.y, tu, pc[k][5]);
                pc[k][6] = ffma2(e3.x, tu, pc[k][6]); pc[k][7] = ffma2(e3.y, tu, pc[k][7]);
            }
        }
    }

    if (valid) {
#pragma unroll
        for (int k = 0; k < 4; k++) {
            float v[16];
#pragma unroll
            for (int p = 0; p < 8; p++) upk(pc[k][p], v[2*p], v[2*p+1]);
            float4* od = reinterpret_cast<float4*>(ocov + b * 256 + rr[k] * 16);
            od[0] = make_float4(v[0],  v[1],  v[2],  v[3]);
            od[1] = make_float4(v[4],  v[5],  v[6],  v[7]);
            od[2] = make_float4(v[8],  v[9],  v[10], v[11]);
            od[3] = make_float4(v[12], v[13], v[14], v[15]);
        }
    }
}

extern "C" void kernel_launch(void* const* d_in, const int* in_sizes, int n_in,
                              void* d_out, int out_size)
{
    const float* gin   = (const float*)d_in[0];
    const float* gmean = (const float*)d_in[1];
    const float* gcov  = (const float*)d_in[2];
    const float* gH    = (const float*)d_in[3];
    const float* gR    = (const float*)d_in[4];
    const float* gF    = (const float*)d_in[5];
    const float* gQ    = (const float*)d_in[6];

    const int nb = in_sizes[1] / 16;
    float* omean = (float*)d_out;
    float* ocov  = omean + (size_t)nb * 16;

    const int blocks = (nb + GB - 1) / GB;
    kf_step<<<blocks, TPB>>>(gin, gmean, gcov, gH, gR, gF, gQ, omean, ocov, nb);
}